// round 11
// baseline (speedup 1.0000x reference)
#include <cuda_runtime.h>
#include <cuda_bf16.h>

#define THREADS 256
#define B_MAX 2048
#define T_DIM 90
#define H_DIM 10

// scratch: sn_in (+folded bias) [B, T, H]  -> 2048*90*10*4 = 7.37 MB
__device__ float g_sn[(size_t)B_MAX * T_DIM * H_DIM];

// Pair-reduce: lanes with (lane & s)==0 end with full reduction of `a`,
// lanes with (lane & s)!=0 end with full reduction of `b`.
__device__ __forceinline__ float pair_reduce(float a, float b, int s, int lane) {
    bool hi = (lane & s) != 0;
    float send = hi ? a : b;
    float recv = __shfl_xor_sync(0xffffffffu, send, s);
    float keep = hi ? b : a;
    return keep + recv;
}

// ---------------------------------------------------------------------------
// Kernel 1: streaming antenna-fuse + hidden GEMV over all (b,t) units.
// One warp per unit, grid-stride. No block barriers in the hot loop.
// ---------------------------------------------------------------------------
__global__ __launch_bounds__(THREADS, 5) void snn_stream_kernel(
    const float* __restrict__ x,       // [B,90,4,256]
    const float* __restrict__ w_ant,   // [4]
    const float* __restrict__ b_ant,   // scalar
    const float* __restrict__ w_hid,   // [10,256]
    const float* __restrict__ b_hid,   // [10]
    int B)
{
    __shared__ float4 s_whid4[10 * 64];   // w_hid as float4: [h][64]
    __shared__ float  s_bias[10];

    const int tid  = threadIdx.x;
    const int warp = tid >> 5;
    const int lane = tid & 31;

    const float4* wh4 = reinterpret_cast<const float4*>(w_hid);
    for (int i = tid; i < 640; i += THREADS) s_whid4[i] = wh4[i];
    __syncthreads();
    if (tid < 10) {
        const float* row = reinterpret_cast<const float*>(&s_whid4[tid * 64]);
        float s = 0.f;
        #pragma unroll 8
        for (int d = 0; d < 256; ++d) s += row[d];
        s_bias[tid] = b_hid[tid] + b_ant[0] * s;   // fold conv bias into hidden bias
    }
    const float wa0 = w_ant[0], wa1 = w_ant[1], wa2 = w_ant[2], wa3 = w_ant[3];
    __syncthreads();

    // loop-invariant per-lane reduction metadata
    const int h_mine = (lane & 2) ? (8 + ((lane >> 4) & 1))
                                  : (((lane >> 2) & 1) * 4 + ((lane >> 3) & 1) * 2 + ((lane >> 4) & 1));
    const bool writer = ((lane & 1) == 0) && (((lane & 2) == 0) || ((lane & 12) == 0));
    const float bias_mine = s_bias[h_mine];
    const float4* wl0 = s_whid4 + lane;   // per-lane weight base (half1 uses +32)

    const int total_units = B * T_DIM;
    const int warps_total = gridDim.x * (THREADS / 32);
    const int wgid = blockIdx.x * (THREADS / 32) + warp;

    for (int u = wgid; u < total_units; u += warps_total) {
        // u = b*90 + t ; x slice base = u * (4*256 floats) = u * 256 float4
        const float4* xw = reinterpret_cast<const float4*>(x) + (size_t)u * 256 + lane;
        float acc[10];

        // ---- half 0: all 4 antennas, d-offset 0 ----
        {
            float4 a0 = __ldcs(xw      );
            float4 a1 = __ldcs(xw + 64 );
            float4 a2 = __ldcs(xw + 128);
            float4 a3 = __ldcs(xw + 192);
            float4 f;
            f.x = fmaf(a3.x, wa3, fmaf(a2.x, wa2, fmaf(a1.x, wa1, a0.x * wa0)));
            f.y = fmaf(a3.y, wa3, fmaf(a2.y, wa2, fmaf(a1.y, wa1, a0.y * wa0)));
            f.z = fmaf(a3.z, wa3, fmaf(a2.z, wa2, fmaf(a1.z, wa1, a0.z * wa0)));
            f.w = fmaf(a3.w, wa3, fmaf(a2.w, wa2, fmaf(a1.w, wa1, a0.w * wa0)));
            #pragma unroll
            for (int h = 0; h < 10; ++h) {
                float4 w = wl0[h * 64];
                float r;
                r = f.x * w.x;
                r = fmaf(f.y, w.y, r);
                r = fmaf(f.z, w.z, r);
                r = fmaf(f.w, w.w, r);
                acc[h] = r;
            }
        }

        // ---- half 1: all 4 antennas, d-offset 32 (float4 units) ----
        {
            float4 a0 = __ldcs(xw + 32 );
            float4 a1 = __ldcs(xw + 96 );
            float4 a2 = __ldcs(xw + 160);
            float4 a3 = __ldcs(xw + 224);
            float4 f;
            f.x = fmaf(a3.x, wa3, fmaf(a2.x, wa2, fmaf(a1.x, wa1, a0.x * wa0)));
            f.y = fmaf(a3.y, wa3, fmaf(a2.y, wa2, fmaf(a1.y, wa1, a0.y * wa0)));
            f.z = fmaf(a3.z, wa3, fmaf(a2.z, wa2, fmaf(a1.z, wa1, a0.z * wa0)));
            f.w = fmaf(a3.w, wa3, fmaf(a2.w, wa2, fmaf(a1.w, wa1, a0.w * wa0)));
            #pragma unroll
            for (int h = 0; h < 10; ++h) {
                float4 w = wl0[h * 64 + 32];
                float r = acc[h];
                r = fmaf(f.x, w.x, r);
                r = fmaf(f.y, w.y, r);
                r = fmaf(f.z, w.z, r);
                r = fmaf(f.w, w.w, r);
                acc[h] = r;
            }
        }

        // ---- log-packed warp reduction: 12 SHFL ----
        float v0 = pair_reduce(acc[0], acc[1], 16, lane);
        float v1 = pair_reduce(acc[2], acc[3], 16, lane);
        float v2 = pair_reduce(acc[4], acc[5], 16, lane);
        float v3 = pair_reduce(acc[6], acc[7], 16, lane);
        float v4 = pair_reduce(acc[8], acc[9], 16, lane);
        float u0 = pair_reduce(v0, v1, 8, lane);
        float u1 = pair_reduce(v2, v3, 8, lane);
        v4 += __shfl_xor_sync(0xffffffffu, v4, 8);
        float w0r = pair_reduce(u0, u1, 4, lane);
        v4 += __shfl_xor_sync(0xffffffffu, v4, 4);
        float z = pair_reduce(w0r, v4, 2, lane);
        z += __shfl_xor_sync(0xffffffffu, z, 1);

        if (writer) g_sn[(size_t)u * H_DIM + h_mine] = z + bias_mine;
    }
}

// ---------------------------------------------------------------------------
// Kernel 2: Leaky scan over T per batch row + time fuse + output + softmax.
// One warp per row; lanes < 10 carry the recurrence.
// ---------------------------------------------------------------------------
__global__ __launch_bounds__(THREADS, 4) void snn_scan_kernel(
    const float* __restrict__ w_time,  // [90]
    const float* __restrict__ b_time,  // scalar
    const float* __restrict__ w_out,   // [2,10]
    const float* __restrict__ b_out,   // [2]
    float* __restrict__ out,           // [B,2]
    int B)
{
    __shared__ float s_wtime[T_DIM];

    const int tid  = threadIdx.x;
    const int warp = tid >> 5;
    const int lane = tid & 31;

    if (tid < T_DIM) s_wtime[tid] = w_time[tid];
    __syncthreads();

    const int b = blockIdx.x * (THREADS / 32) + warp;
    if (b >= B) return;

    float fused = 0.f;
    if (lane < H_DIM) {
        const float* sn = g_sn + (size_t)b * T_DIM * H_DIM + lane;
        float mem = 0.f, acc = 0.f;
        #pragma unroll 6
        for (int t = 0; t < T_DIM; ++t) {
            float inp = sn[t * H_DIM];   // bias already folded in
            // reset from PREVIOUS mem, reset_mechanism='zero'
            float mem_new = (mem > 1.0f) ? 0.0f : fmaf(0.95f, mem, inp);
            if (mem_new > 1.0f) acc += s_wtime[t];   // spike: Heaviside(mem_new-1)
            mem = mem_new;
        }
        fused = acc + b_time[0];
    }

    float c0 = (lane < H_DIM) ? fused * __ldg(w_out + lane)          : 0.f;
    float c1 = (lane < H_DIM) ? fused * __ldg(w_out + H_DIM + lane)  : 0.f;
    #pragma unroll
    for (int s = 16; s > 0; s >>= 1) {
        c0 += __shfl_xor_sync(0xffffffffu, c0, s);
        c1 += __shfl_xor_sync(0xffffffffu, c1, s);
    }
    if (lane == 0) {
        float o0 = c0 + b_out[0];
        float o1 = c1 + b_out[1];
        float m  = fmaxf(o0, o1);
        float e0 = __expf(o0 - m);
        float e1 = __expf(o1 - m);
        float inv = 1.0f / (e0 + e1);
        out[2 * b]     = e0 * inv;
        out[2 * b + 1] = e1 * inv;
    }
}

extern "C" void kernel_launch(void* const* d_in, const int* in_sizes, int n_in,
                              void* d_out, int out_size) {
    const float* x      = (const float*)d_in[0];
    const float* w_ant  = (const float*)d_in[1];
    const float* b_ant  = (const float*)d_in[2];
    const float* w_hid  = (const float*)d_in[3];
    const float* b_hid  = (const float*)d_in[4];
    const float* w_time = (const float*)d_in[5];
    const float* b_time = (const float*)d_in[6];
    const float* w_out  = (const float*)d_in[7];
    const float* b_out  = (const float*)d_in[8];
    float* out = (float*)d_out;

    int B = in_sizes[0] / (T_DIM * 4 * 256);   // 2048
    if (B > B_MAX) B = B_MAX;                  // scratch bound (dataset B=2048)

    // Kernel 1: one wave at occ 5 -> 148*5 = 740 CTAs, warps grid-stride
    // over 184320 (b,t) units (~31 units/warp, imbalance <= 1 unit).
    snn_stream_kernel<<<740, THREADS>>>(x, w_ant, b_ant, w_hid, b_hid, B);

    // Kernel 2: one warp per batch row.
    const int grid2 = (B + (THREADS / 32) - 1) / (THREADS / 32);
    snn_scan_kernel<<<grid2, THREADS>>>(w_time, b_time, w_out, b_out, out, B);
}

// round 12
// speedup vs baseline: 1.1086x; 1.1086x over previous
#include <cuda_runtime.h>
#include <cuda_bf16.h>

#define THREADS 256
#define B_MAX 2048
#define T_DIM 90
#define T_PAD 96
#define H_DIM 10

// scratch: sn_in (+folded bias), TRANSPOSED [B, H, T_PAD]
// 2048*10*96*4 = 7.86 MB. Zero-initialized at module load; t in [90,96)
// is never written and never used.
__device__ float g_sn[(size_t)B_MAX * H_DIM * T_PAD];

// Pair-reduce: lanes with (lane & s)==0 end with full reduction of `a`,
// lanes with (lane & s)!=0 end with full reduction of `b`.
__device__ __forceinline__ float pair_reduce(float a, float b, int s, int lane) {
    bool hi = (lane & s) != 0;
    float send = hi ? a : b;
    float recv = __shfl_xor_sync(0xffffffffu, send, s);
    float keep = hi ? b : a;
    return keep + recv;
}

// ---------------------------------------------------------------------------
// Kernel 1: streaming antenna-fuse + hidden GEMV over all (b,t) units.
// One warp per unit, grid-stride. No block barriers in the hot loop.
// ---------------------------------------------------------------------------
__global__ __launch_bounds__(THREADS, 5) void snn_stream_kernel(
    const float* __restrict__ x,       // [B,90,4,256]
    const float* __restrict__ w_ant,   // [4]
    const float* __restrict__ b_ant,   // scalar
    const float* __restrict__ w_hid,   // [10,256]
    const float* __restrict__ b_hid,   // [10]
    int B)
{
    __shared__ float4 s_whid4[10 * 64];   // w_hid as float4: [h][64]
    __shared__ float  s_bias[10];

    const int tid  = threadIdx.x;
    const int warp = tid >> 5;
    const int lane = tid & 31;

    const float4* wh4 = reinterpret_cast<const float4*>(w_hid);
    for (int i = tid; i < 640; i += THREADS) s_whid4[i] = wh4[i];
    __syncthreads();
    if (tid < 10) {
        const float* row = reinterpret_cast<const float*>(&s_whid4[tid * 64]);
        float s = 0.f;
        #pragma unroll 8
        for (int d = 0; d < 256; ++d) s += row[d];
        s_bias[tid] = b_hid[tid] + b_ant[0] * s;   // fold conv bias into hidden bias
    }
    const float wa0 = w_ant[0], wa1 = w_ant[1], wa2 = w_ant[2], wa3 = w_ant[3];
    __syncthreads();

    // loop-invariant per-lane reduction metadata
    const int h_mine = (lane & 2) ? (8 + ((lane >> 4) & 1))
                                  : (((lane >> 2) & 1) * 4 + ((lane >> 3) & 1) * 2 + ((lane >> 4) & 1));
    const bool writer = ((lane & 1) == 0) && (((lane & 2) == 0) || ((lane & 12) == 0));
    const float bias_mine = s_bias[h_mine];
    const float4* wl0 = s_whid4 + lane;   // per-lane weight base (half1 uses +32)

    const int total_units = B * T_DIM;
    const int warps_total = gridDim.x * (THREADS / 32);
    const int wgid = blockIdx.x * (THREADS / 32) + warp;

    for (int u = wgid; u < total_units; u += warps_total) {
        // u = b*90 + t ; x slice base = u * (4*256 floats) = u * 256 float4
        const float4* xw = reinterpret_cast<const float4*>(x) + (size_t)u * 256 + lane;
        float acc[10];

        // ---- half 0: all 4 antennas, d-offset 0 ----
        {
            float4 a0 = __ldcs(xw      );
            float4 a1 = __ldcs(xw + 64 );
            float4 a2 = __ldcs(xw + 128);
            float4 a3 = __ldcs(xw + 192);
            float4 f;
            f.x = fmaf(a3.x, wa3, fmaf(a2.x, wa2, fmaf(a1.x, wa1, a0.x * wa0)));
            f.y = fmaf(a3.y, wa3, fmaf(a2.y, wa2, fmaf(a1.y, wa1, a0.y * wa0)));
            f.z = fmaf(a3.z, wa3, fmaf(a2.z, wa2, fmaf(a1.z, wa1, a0.z * wa0)));
            f.w = fmaf(a3.w, wa3, fmaf(a2.w, wa2, fmaf(a1.w, wa1, a0.w * wa0)));
            #pragma unroll
            for (int h = 0; h < 10; ++h) {
                float4 w = wl0[h * 64];
                float r;
                r = f.x * w.x;
                r = fmaf(f.y, w.y, r);
                r = fmaf(f.z, w.z, r);
                r = fmaf(f.w, w.w, r);
                acc[h] = r;
            }
        }

        // ---- half 1: all 4 antennas, d-offset 32 (float4 units) ----
        {
            float4 a0 = __ldcs(xw + 32 );
            float4 a1 = __ldcs(xw + 96 );
            float4 a2 = __ldcs(xw + 160);
            float4 a3 = __ldcs(xw + 224);
            float4 f;
            f.x = fmaf(a3.x, wa3, fmaf(a2.x, wa2, fmaf(a1.x, wa1, a0.x * wa0)));
            f.y = fmaf(a3.y, wa3, fmaf(a2.y, wa2, fmaf(a1.y, wa1, a0.y * wa0)));
            f.z = fmaf(a3.z, wa3, fmaf(a2.z, wa2, fmaf(a1.z, wa1, a0.z * wa0)));
            f.w = fmaf(a3.w, wa3, fmaf(a2.w, wa2, fmaf(a1.w, wa1, a0.w * wa0)));
            #pragma unroll
            for (int h = 0; h < 10; ++h) {
                float4 w = wl0[h * 64 + 32];
                float r = acc[h];
                r = fmaf(f.x, w.x, r);
                r = fmaf(f.y, w.y, r);
                r = fmaf(f.z, w.z, r);
                r = fmaf(f.w, w.w, r);
                acc[h] = r;
            }
        }

        // ---- log-packed warp reduction: 12 SHFL ----
        float v0 = pair_reduce(acc[0], acc[1], 16, lane);
        float v1 = pair_reduce(acc[2], acc[3], 16, lane);
        float v2 = pair_reduce(acc[4], acc[5], 16, lane);
        float v3 = pair_reduce(acc[6], acc[7], 16, lane);
        float v4 = pair_reduce(acc[8], acc[9], 16, lane);
        float u0 = pair_reduce(v0, v1, 8, lane);
        float u1 = pair_reduce(v2, v3, 8, lane);
        v4 += __shfl_xor_sync(0xffffffffu, v4, 8);
        float w0r = pair_reduce(u0, u1, 4, lane);
        v4 += __shfl_xor_sync(0xffffffffu, v4, 4);
        float z = pair_reduce(w0r, v4, 2, lane);
        z += __shfl_xor_sync(0xffffffffu, z, 1);

        if (writer) {
            int b = u / T_DIM;
            int t = u - b * T_DIM;
            g_sn[((size_t)b * H_DIM + h_mine) * T_PAD + t] = z + bias_mine;
        }
    }
}

// ---------------------------------------------------------------------------
// Kernel 2: Leaky scan per (b,h) THREAD, vectorized float4 reads of the
// transposed scratch, then per-b output GEMV + softmax.
// Block = 320 threads = 32 batch rows (10 h-threads each).
// ---------------------------------------------------------------------------
__global__ __launch_bounds__(320, 4) void snn_scan_kernel(
    const float* __restrict__ w_time,  // [90]
    const float* __restrict__ b_time,  // scalar
    const float* __restrict__ w_out,   // [2,10]
    const float* __restrict__ b_out,   // [2]
    float* __restrict__ out,           // [B,2]
    int B)
{
    __shared__ float s_wtime[T_DIM];
    __shared__ float s_f[32][H_DIM];

    const int tid = threadIdx.x;
    if (tid < T_DIM) s_wtime[tid] = w_time[tid];
    __syncthreads();

    const int b_local = tid / H_DIM;          // 0..31
    const int h       = tid - b_local * H_DIM;
    const int b       = blockIdx.x * 32 + b_local;

    if (b < B) {
        const float4* row = reinterpret_cast<const float4*>(
            g_sn + ((size_t)b * H_DIM + h) * T_PAD);
        float mem = 0.f, acc = 0.f;

        #define LEAKY_STEP(val, tt)                                          \
            {                                                                \
                float mem_new = (mem > 1.0f) ? 0.0f : fmaf(0.95f, mem, (val)); \
                if (mem_new > 1.0f) acc += s_wtime[tt];                      \
                mem = mem_new;                                               \
            }

        #pragma unroll
        for (int c = 0; c < 22; ++c) {        // t = 0..87
            float4 v = row[c];
            LEAKY_STEP(v.x, 4 * c + 0);
            LEAKY_STEP(v.y, 4 * c + 1);
            LEAKY_STEP(v.z, 4 * c + 2);
            LEAKY_STEP(v.w, 4 * c + 3);
        }
        {                                      // t = 88, 89 (padding unused)
            float4 v = row[22];
            LEAKY_STEP(v.x, 88);
            LEAKY_STEP(v.y, 89);
        }
        #undef LEAKY_STEP

        s_f[b_local][h] = acc + b_time[0];
    }
    __syncthreads();

    // 32 threads: one per batch row -> O=2 GEMV + softmax
    if (tid < 32) {
        const int bb = blockIdx.x * 32 + tid;
        if (bb < B) {
            float o0 = b_out[0], o1 = b_out[1];
            #pragma unroll
            for (int hh = 0; hh < H_DIM; ++hh) {
                float fv = s_f[tid][hh];
                o0 = fmaf(fv, __ldg(w_out + hh),         o0);
                o1 = fmaf(fv, __ldg(w_out + H_DIM + hh), o1);
            }
            float m  = fmaxf(o0, o1);
            float e0 = __expf(o0 - m);
            float e1 = __expf(o1 - m);
            float inv = 1.0f / (e0 + e1);
            out[2 * bb]     = e0 * inv;
            out[2 * bb + 1] = e1 * inv;
        }
    }
}

extern "C" void kernel_launch(void* const* d_in, const int* in_sizes, int n_in,
                              void* d_out, int out_size) {
    const float* x      = (const float*)d_in[0];
    const float* w_ant  = (const float*)d_in[1];
    const float* b_ant  = (const float*)d_in[2];
    const float* w_hid  = (const float*)d_in[3];
    const float* b_hid  = (const float*)d_in[4];
    const float* w_time = (const float*)d_in[5];
    const float* b_time = (const float*)d_in[6];
    const float* w_out  = (const float*)d_in[7];
    const float* b_out  = (const float*)d_in[8];
    float* out = (float*)d_out;

    int B = in_sizes[0] / (T_DIM * 4 * 256);   // 2048
    if (B > B_MAX) B = B_MAX;                  // scratch bound (dataset B=2048)

    // Kernel 1: one wave at occ 5 -> 148*5 = 740 CTAs, warps grid-stride
    // over 184320 (b,t) units (~31 units/warp, imbalance <= 1 unit).
    snn_stream_kernel<<<740, THREADS>>>(x, w_ant, b_ant, w_hid, b_hid, B);

    // Kernel 2: 32 rows per 320-thread block.
    const int grid2 = (B + 31) / 32;
    snn_scan_kernel<<<grid2, 320>>>(w_time, b_time, w_out, b_out, out, B);
}

// round 13
// speedup vs baseline: 1.1203x; 1.0106x over previous
#include <cuda_runtime.h>
#include <cuda_bf16.h>

#define THREADS 256
#define B_MAX 2048
#define T_DIM 90
#define T_PAD 96
#define H_DIM 10

// scratch: sn_in (+folded bias), TRANSPOSED [B, H, T_PAD]
// 2048*10*96*4 = 7.86 MB. t in [90,96) never written, never used.
__device__ float g_sn[(size_t)B_MAX * H_DIM * T_PAD];

// Pair-reduce: lanes with (lane & s)==0 end with full reduction of `a`,
// lanes with (lane & s)!=0 end with full reduction of `b`.
__device__ __forceinline__ float pair_reduce(float a, float b, int s, int lane) {
    bool hi = (lane & s) != 0;
    float send = hi ? a : b;
    float recv = __shfl_xor_sync(0xffffffffu, send, s);
    float keep = hi ? b : a;
    return keep + recv;
}

// ---------------------------------------------------------------------------
// Kernel 1: streaming antenna-fuse + hidden GEMV over all (b,t) units.
// One warp per unit, grid-stride. No block barriers in the hot loop.
// ---------------------------------------------------------------------------
__global__ __launch_bounds__(THREADS, 6) void snn_stream_kernel(
    const float* __restrict__ x,       // [B,90,4,256]
    const float* __restrict__ w_ant,   // [4]
    const float* __restrict__ b_ant,   // scalar
    const float* __restrict__ w_hid,   // [10,256]
    const float* __restrict__ b_hid,   // [10]
    int B)
{
    __shared__ float4 s_whid4[10 * 64];   // w_hid as float4: [h][64]
    __shared__ float  s_bias[10];

    const int tid  = threadIdx.x;
    const int warp = tid >> 5;
    const int lane = tid & 31;

    const float4* wh4 = reinterpret_cast<const float4*>(w_hid);
    for (int i = tid; i < 640; i += THREADS) s_whid4[i] = wh4[i];
    __syncthreads();
    if (tid < 10) {
        const float* row = reinterpret_cast<const float*>(&s_whid4[tid * 64]);
        float s = 0.f;
        #pragma unroll 8
        for (int d = 0; d < 256; ++d) s += row[d];
        s_bias[tid] = b_hid[tid] + b_ant[0] * s;   // fold conv bias into hidden bias
    }
    const float wa0 = w_ant[0], wa1 = w_ant[1], wa2 = w_ant[2], wa3 = w_ant[3];
    __syncthreads();

    // loop-invariant per-lane reduction metadata
    const int h_mine = (lane & 2) ? (8 + ((lane >> 4) & 1))
                                  : (((lane >> 2) & 1) * 4 + ((lane >> 3) & 1) * 2 + ((lane >> 4) & 1));
    const bool writer = ((lane & 1) == 0) && (((lane & 2) == 0) || ((lane & 12) == 0));
    const float bias_mine = s_bias[h_mine];
    const float4* wl0 = s_whid4 + lane;   // per-lane weight base (half1 uses +32)

    const int total_units = B * T_DIM;
    const int warps_total = gridDim.x * (THREADS / 32);
    const int wgid = blockIdx.x * (THREADS / 32) + warp;

    for (int u = wgid; u < total_units; u += warps_total) {
        // u = b*90 + t ; x slice base = u * (4*256 floats) = u * 256 float4
        const float4* xw = reinterpret_cast<const float4*>(x) + (size_t)u * 256 + lane;
        float acc[10];

        // ---- half 0: all 4 antennas, d-offset 0 ----
        {
            float4 a0 = __ldcs(xw      );
            float4 a1 = __ldcs(xw + 64 );
            float4 a2 = __ldcs(xw + 128);
            float4 a3 = __ldcs(xw + 192);
            float4 f;
            f.x = fmaf(a3.x, wa3, fmaf(a2.x, wa2, fmaf(a1.x, wa1, a0.x * wa0)));
            f.y = fmaf(a3.y, wa3, fmaf(a2.y, wa2, fmaf(a1.y, wa1, a0.y * wa0)));
            f.z = fmaf(a3.z, wa3, fmaf(a2.z, wa2, fmaf(a1.z, wa1, a0.z * wa0)));
            f.w = fmaf(a3.w, wa3, fmaf(a2.w, wa2, fmaf(a1.w, wa1, a0.w * wa0)));
            #pragma unroll
            for (int h = 0; h < 10; ++h) {
                float4 w = wl0[h * 64];
                float r;
                r = f.x * w.x;
                r = fmaf(f.y, w.y, r);
                r = fmaf(f.z, w.z, r);
                r = fmaf(f.w, w.w, r);
                acc[h] = r;
            }
        }

        // ---- half 1: all 4 antennas, d-offset 32 (float4 units) ----
        {
            float4 a0 = __ldcs(xw + 32 );
            float4 a1 = __ldcs(xw + 96 );
            float4 a2 = __ldcs(xw + 160);
            float4 a3 = __ldcs(xw + 224);
            float4 f;
            f.x = fmaf(a3.x, wa3, fmaf(a2.x, wa2, fmaf(a1.x, wa1, a0.x * wa0)));
            f.y = fmaf(a3.y, wa3, fmaf(a2.y, wa2, fmaf(a1.y, wa1, a0.y * wa0)));
            f.z = fmaf(a3.z, wa3, fmaf(a2.z, wa2, fmaf(a1.z, wa1, a0.z * wa0)));
            f.w = fmaf(a3.w, wa3, fmaf(a2.w, wa2, fmaf(a1.w, wa1, a0.w * wa0)));
            #pragma unroll
            for (int h = 0; h < 10; ++h) {
                float4 w = wl0[h * 64 + 32];
                float r = acc[h];
                r = fmaf(f.x, w.x, r);
                r = fmaf(f.y, w.y, r);
                r = fmaf(f.z, w.z, r);
                r = fmaf(f.w, w.w, r);
                acc[h] = r;
            }
        }

        // ---- log-packed warp reduction: 12 SHFL ----
        float v0 = pair_reduce(acc[0], acc[1], 16, lane);
        float v1 = pair_reduce(acc[2], acc[3], 16, lane);
        float v2 = pair_reduce(acc[4], acc[5], 16, lane);
        float v3 = pair_reduce(acc[6], acc[7], 16, lane);
        float v4 = pair_reduce(acc[8], acc[9], 16, lane);
        float u0 = pair_reduce(v0, v1, 8, lane);
        float u1 = pair_reduce(v2, v3, 8, lane);
        v4 += __shfl_xor_sync(0xffffffffu, v4, 8);
        float w0r = pair_reduce(u0, u1, 4, lane);
        v4 += __shfl_xor_sync(0xffffffffu, v4, 4);
        float z = pair_reduce(w0r, v4, 2, lane);
        z += __shfl_xor_sync(0xffffffffu, z, 1);

        if (writer) {
            int b = u / T_DIM;
            int t = u - b * T_DIM;
            g_sn[((size_t)b * H_DIM + h_mine) * T_PAD + t] = z + bias_mine;
        }
    }
}

// ---------------------------------------------------------------------------
// Kernel 2: Leaky scan per (b,h) THREAD, vectorized float4 reads of the
// transposed scratch, then per-b output GEMV + softmax.
// Small blocks (80 thr = 8 rows) -> 256 blocks spread over all 148 SMs.
// ---------------------------------------------------------------------------
#define BLK2_ROWS 8
#define BLK2_THREADS (BLK2_ROWS * H_DIM)   // 80

__global__ __launch_bounds__(BLK2_THREADS, 16) void snn_scan_kernel(
    const float* __restrict__ w_time,  // [90]
    const float* __restrict__ b_time,  // scalar
    const float* __restrict__ w_out,   // [2,10]
    const float* __restrict__ b_out,   // [2]
    float* __restrict__ out,           // [B,2]
    int B)
{
    __shared__ float s_wtime[T_DIM];
    __shared__ float s_f[BLK2_ROWS][H_DIM];

    const int tid = threadIdx.x;
    for (int i = tid; i < T_DIM; i += BLK2_THREADS) s_wtime[i] = w_time[i];
    __syncthreads();

    const int b_local = tid / H_DIM;          // 0..7
    const int h       = tid - b_local * H_DIM;
    const int b       = blockIdx.x * BLK2_ROWS + b_local;

    if (b < B) {
        const float4* row = reinterpret_cast<const float4*>(
            g_sn + ((size_t)b * H_DIM + h) * T_PAD);
        float mem = 0.f, acc = 0.f;

        #define LEAKY_STEP(val, tt)                                            \
            {                                                                  \
                float mem_new = (mem > 1.0f) ? 0.0f : fmaf(0.95f, mem, (val)); \
                if (mem_new > 1.0f) acc += s_wtime[tt];                        \
                mem = mem_new;                                                 \
            }

        #pragma unroll
        for (int c = 0; c < 22; ++c) {        // t = 0..87
            float4 v = row[c];
            LEAKY_STEP(v.x, 4 * c + 0);
            LEAKY_STEP(v.y, 4 * c + 1);
            LEAKY_STEP(v.z, 4 * c + 2);
            LEAKY_STEP(v.w, 4 * c + 3);
        }
        {                                      // t = 88, 89 (padding unused)
            float4 v = row[22];
            LEAKY_STEP(v.x, 88);
            LEAKY_STEP(v.y, 89);
        }
        #undef LEAKY_STEP

        s_f[b_local][h] = acc + b_time[0];
    }
    __syncthreads();

    // BLK2_ROWS threads: one per batch row -> O=2 GEMV + softmax
    if (tid < BLK2_ROWS) {
        const int bb = blockIdx.x * BLK2_ROWS + tid;
        if (bb < B) {
            float o0 = b_out[0], o1 = b_out[1];
            #pragma unroll
            for (int hh = 0; hh < H_DIM; ++hh) {
                float fv = s_f[tid][hh];
                o0 = fmaf(fv, __ldg(w_out + hh),         o0);
                o1 = fmaf(fv, __ldg(w_out + H_DIM + hh), o1);
            }
            float m  = fmaxf(o0, o1);
            float e0 = __expf(o0 - m);
            float e1 = __expf(o1 - m);
            float inv = 1.0f / (e0 + e1);
            out[2 * bb]     = e0 * inv;
            out[2 * bb + 1] = e1 * inv;
        }
    }
}

extern "C" void kernel_launch(void* const* d_in, const int* in_sizes, int n_in,
                              void* d_out, int out_size) {
    const float* x      = (const float*)d_in[0];
    const float* w_ant  = (const float*)d_in[1];
    const float* b_ant  = (const float*)d_in[2];
    const float* w_hid  = (const float*)d_in[3];
    const float* b_hid  = (const float*)d_in[4];
    const float* w_time = (const float*)d_in[5];
    const float* b_time = (const float*)d_in[6];
    const float* w_out  = (const float*)d_in[7];
    const float* b_out  = (const float*)d_in[8];
    float* out = (float*)d_out;

    int B = in_sizes[0] / (T_DIM * 4 * 256);   // 2048
    if (B > B_MAX) B = B_MAX;                  // scratch bound (dataset B=2048)

    // Kernel 1: one wave at occ 6 -> 148*6 = 888 CTAs; 7104 warps grid-stride
    // over 184320 (b,t) units (25.9 +/- 1 units per warp, balanced).
    snn_stream_kernel<<<888, THREADS>>>(x, w_ant, b_ant, w_hid, b_hid, B);

    // Kernel 2: 8 rows per 80-thread block -> 256 blocks across all SMs.
    const int grid2 = (B + BLK2_ROWS - 1) / BLK2_ROWS;
    snn_scan_kernel<<<grid2, BLK2_THREADS>>>(w_time, b_time, w_out, b_out, out, B);
}

// round 14
// speedup vs baseline: 1.1546x; 1.0306x over previous
#include <cuda_runtime.h>
#include <cuda_bf16.h>

#define THREADS 256
#define B_MAX 2048
#define T_DIM 90
#define H_DIM 10

// scratch: sn_in (+folded bias), flat [B, T, H] -> 2048*90*10*4 = 7.37 MB
__device__ float g_sn[(size_t)B_MAX * T_DIM * H_DIM];

// Pair-reduce: lanes with (lane & s)==0 end with full reduction of `a`,
// lanes with (lane & s)!=0 end with full reduction of `b`.
__device__ __forceinline__ float pair_reduce(float a, float b, int s, int lane) {
    bool hi = (lane & s) != 0;
    float send = hi ? a : b;
    float recv = __shfl_xor_sync(0xffffffffu, send, s);
    float keep = hi ? b : a;
    return keep + recv;
}

// ---------------------------------------------------------------------------
// Kernel 1 (identical to R11's k1 — measured ~114 us): streaming
// antenna-fuse + hidden GEMV over all (b,t) units. One warp per unit,
// grid-stride, no block barriers in the hot loop, flat 40B burst store.
// ---------------------------------------------------------------------------
__global__ __launch_bounds__(THREADS, 5) void snn_stream_kernel(
    const float* __restrict__ x,       // [B,90,4,256]
    const float* __restrict__ w_ant,   // [4]
    const float* __restrict__ b_ant,   // scalar
    const float* __restrict__ w_hid,   // [10,256]
    const float* __restrict__ b_hid,   // [10]
    int B)
{
    __shared__ float4 s_whid4[10 * 64];   // w_hid as float4: [h][64]
    __shared__ float  s_bias[10];

    const int tid  = threadIdx.x;
    const int warp = tid >> 5;
    const int lane = tid & 31;

    const float4* wh4 = reinterpret_cast<const float4*>(w_hid);
    for (int i = tid; i < 640; i += THREADS) s_whid4[i] = wh4[i];
    __syncthreads();
    if (tid < 10) {
        const float* row = reinterpret_cast<const float*>(&s_whid4[tid * 64]);
        float s = 0.f;
        #pragma unroll 8
        for (int d = 0; d < 256; ++d) s += row[d];
        s_bias[tid] = b_hid[tid] + b_ant[0] * s;   // fold conv bias into hidden bias
    }
    const float wa0 = w_ant[0], wa1 = w_ant[1], wa2 = w_ant[2], wa3 = w_ant[3];
    __syncthreads();

    // loop-invariant per-lane reduction metadata
    const int h_mine = (lane & 2) ? (8 + ((lane >> 4) & 1))
                                  : (((lane >> 2) & 1) * 4 + ((lane >> 3) & 1) * 2 + ((lane >> 4) & 1));
    const bool writer = ((lane & 1) == 0) && (((lane & 2) == 0) || ((lane & 12) == 0));
    const float bias_mine = s_bias[h_mine];
    const float4* wl0 = s_whid4 + lane;   // per-lane weight base (half1 uses +32)

    const int total_units = B * T_DIM;
    const int warps_total = gridDim.x * (THREADS / 32);
    const int wgid = blockIdx.x * (THREADS / 32) + warp;

    for (int u = wgid; u < total_units; u += warps_total) {
        // u = b*90 + t ; x slice base = u * (4*256 floats) = u * 256 float4
        const float4* xw = reinterpret_cast<const float4*>(x) + (size_t)u * 256 + lane;
        float acc[10];

        // ---- half 0: all 4 antennas, d-offset 0 ----
        {
            float4 a0 = __ldcs(xw      );
            float4 a1 = __ldcs(xw + 64 );
            float4 a2 = __ldcs(xw + 128);
            float4 a3 = __ldcs(xw + 192);
            float4 f;
            f.x = fmaf(a3.x, wa3, fmaf(a2.x, wa2, fmaf(a1.x, wa1, a0.x * wa0)));
            f.y = fmaf(a3.y, wa3, fmaf(a2.y, wa2, fmaf(a1.y, wa1, a0.y * wa0)));
            f.z = fmaf(a3.z, wa3, fmaf(a2.z, wa2, fmaf(a1.z, wa1, a0.z * wa0)));
            f.w = fmaf(a3.w, wa3, fmaf(a2.w, wa2, fmaf(a1.w, wa1, a0.w * wa0)));
            #pragma unroll
            for (int h = 0; h < 10; ++h) {
                float4 w = wl0[h * 64];
                float r;
                r = f.x * w.x;
                r = fmaf(f.y, w.y, r);
                r = fmaf(f.z, w.z, r);
                r = fmaf(f.w, w.w, r);
                acc[h] = r;
            }
        }

        // ---- half 1: all 4 antennas, d-offset 32 (float4 units) ----
        {
            float4 a0 = __ldcs(xw + 32 );
            float4 a1 = __ldcs(xw + 96 );
            float4 a2 = __ldcs(xw + 160);
            float4 a3 = __ldcs(xw + 224);
            float4 f;
            f.x = fmaf(a3.x, wa3, fmaf(a2.x, wa2, fmaf(a1.x, wa1, a0.x * wa0)));
            f.y = fmaf(a3.y, wa3, fmaf(a2.y, wa2, fmaf(a1.y, wa1, a0.y * wa0)));
            f.z = fmaf(a3.z, wa3, fmaf(a2.z, wa2, fmaf(a1.z, wa1, a0.z * wa0)));
            f.w = fmaf(a3.w, wa3, fmaf(a2.w, wa2, fmaf(a1.w, wa1, a0.w * wa0)));
            #pragma unroll
            for (int h = 0; h < 10; ++h) {
                float4 w = wl0[h * 64 + 32];
                float r = acc[h];
                r = fmaf(f.x, w.x, r);
                r = fmaf(f.y, w.y, r);
                r = fmaf(f.z, w.z, r);
                r = fmaf(f.w, w.w, r);
                acc[h] = r;
            }
        }

        // ---- log-packed warp reduction: 12 SHFL ----
        float v0 = pair_reduce(acc[0], acc[1], 16, lane);
        float v1 = pair_reduce(acc[2], acc[3], 16, lane);
        float v2 = pair_reduce(acc[4], acc[5], 16, lane);
        float v3 = pair_reduce(acc[6], acc[7], 16, lane);
        float v4 = pair_reduce(acc[8], acc[9], 16, lane);
        float u0 = pair_reduce(v0, v1, 8, lane);
        float u1 = pair_reduce(v2, v3, 8, lane);
        v4 += __shfl_xor_sync(0xffffffffu, v4, 8);
        float w0r = pair_reduce(u0, u1, 4, lane);
        v4 += __shfl_xor_sync(0xffffffffu, v4, 4);
        float z = pair_reduce(w0r, v4, 2, lane);
        z += __shfl_xor_sync(0xffffffffu, z, 1);

        if (writer) g_sn[(size_t)u * H_DIM + h_mine] = z + bias_mine;
    }
}

// ---------------------------------------------------------------------------
// Kernel 2: one WARP per batch row. Warp cooperatively loads its 900-float
// row (225 float4, fully coalesced) into smem, then lanes < 10 run the
// 90-step Leaky recurrence from smem, shuffle-reduce logits, softmax.
// ---------------------------------------------------------------------------
#define K2_WARPS 8   // rows per block

__global__ __launch_bounds__(THREADS, 6) void snn_scan_kernel(
    const float* __restrict__ w_time,  // [90]
    const float* __restrict__ b_time,  // scalar
    const float* __restrict__ w_out,   // [2,10]
    const float* __restrict__ b_out,   // [2]
    float* __restrict__ out,           // [B,2]
    int B)
{
    __shared__ float  s_wtime[T_DIM];
    __shared__ float4 s_rows[K2_WARPS][225];   // 8 rows x 900 floats = 28.8 KB

    const int tid  = threadIdx.x;
    const int warp = tid >> 5;
    const int lane = tid & 31;

    if (tid < T_DIM) s_wtime[tid] = w_time[tid];
    __syncthreads();

    const int b = blockIdx.x * K2_WARPS + warp;
    if (b >= B) return;

    // cooperative, coalesced row load: 225 float4
    const float4* src = reinterpret_cast<const float4*>(g_sn + (size_t)b * T_DIM * H_DIM);
    #pragma unroll
    for (int i = 0; i < 7; ++i) s_rows[warp][lane + 32 * i] = src[lane + 32 * i];
    if (lane == 0) s_rows[warp][224] = src[224];
    __syncwarp();

    float fused = 0.f;
    if (lane < H_DIM) {
        const float* sr = reinterpret_cast<const float*>(s_rows[warp]);
        float mem = 0.f, acc = 0.f;
        #pragma unroll
        for (int t = 0; t < T_DIM; ++t) {
            float inp = sr[t * H_DIM + lane];   // bias already folded in
            // reset from PREVIOUS mem, reset_mechanism='zero'
            float mem_new = (mem > 1.0f) ? 0.0f : fmaf(0.95f, mem, inp);
            if (mem_new > 1.0f) acc += s_wtime[t];   // spike: Heaviside(mem_new-1)
            mem = mem_new;
        }
        fused = acc + b_time[0];
    }

    float c0 = (lane < H_DIM) ? fused * __ldg(w_out + lane)         : 0.f;
    float c1 = (lane < H_DIM) ? fused * __ldg(w_out + H_DIM + lane) : 0.f;
    #pragma unroll
    for (int s = 16; s > 0; s >>= 1) {
        c0 += __shfl_xor_sync(0xffffffffu, c0, s);
        c1 += __shfl_xor_sync(0xffffffffu, c1, s);
    }
    if (lane == 0) {
        float o0 = c0 + b_out[0];
        float o1 = c1 + b_out[1];
        float m  = fmaxf(o0, o1);
        float e0 = __expf(o0 - m);
        float e1 = __expf(o1 - m);
        float inv = 1.0f / (e0 + e1);
        out[2 * b]     = e0 * inv;
        out[2 * b + 1] = e1 * inv;
    }
}

extern "C" void kernel_launch(void* const* d_in, const int* in_sizes, int n_in,
                              void* d_out, int out_size) {
    const float* x      = (const float*)d_in[0];
    const float* w_ant  = (const float*)d_in[1];
    const float* b_ant  = (const float*)d_in[2];
    const float* w_hid  = (const float*)d_in[3];
    const float* b_hid  = (const float*)d_in[4];
    const float* w_time = (const float*)d_in[5];
    const float* b_time = (const float*)d_in[6];
    const float* w_out  = (const float*)d_in[7];
    const float* b_out  = (const float*)d_in[8];
    float* out = (float*)d_out;

    int B = in_sizes[0] / (T_DIM * 4 * 256);   // 2048
    if (B > B_MAX) B = B_MAX;                  // scratch bound (dataset B=2048)

    // Kernel 1: one wave at occ 5 -> 148*5 = 740 CTAs; warps grid-stride
    // over 184320 (b,t) units (~31 units/warp, imbalance <= 1 unit).
    snn_stream_kernel<<<740, THREADS>>>(x, w_ant, b_ant, w_hid, b_hid, B);

    // Kernel 2: one warp per row, 8 rows per 256-thread block.
    const int grid2 = (B + K2_WARPS - 1) / K2_WARPS;
    snn_scan_kernel<<<grid2, THREADS>>>(w_time, b_time, w_out, b_out, out, B);
}

// round 15
// speedup vs baseline: 1.1982x; 1.0378x over previous
#include <cuda_runtime.h>
#include <cuda_bf16.h>

#define THREADS 256

// Pair-reduce: lanes with (lane & s)==0 end with full reduction of `a`,
// lanes with (lane & s)!=0 end with full reduction of `b`.
__device__ __forceinline__ float pair_reduce(float a, float b, int s, int lane) {
    bool hi = (lane & s) != 0;
    float send = hi ? a : b;
    float recv = __shfl_xor_sync(0xffffffffu, send, s);
    float keep = hi ? b : a;
    return keep + recv;
}

__global__ __launch_bounds__(THREADS, 5) void snn_fused_kernel(
    const float* __restrict__ x,       // [B,T,A,D] = [B,90,4,256]
    const float* __restrict__ w_ant,   // [4]
    const float* __restrict__ b_ant,   // scalar
    const float* __restrict__ w_hid,   // [10,256]
    const float* __restrict__ b_hid,   // [10]
    const float* __restrict__ w_time,  // [90]
    const float* __restrict__ b_time,  // scalar
    const float* __restrict__ w_out,   // [2,10]
    const float* __restrict__ b_out,   // [2]
    float* __restrict__ out,           // [B,2]
    int B)
{
    __shared__ float4 s_whid4[10 * 64];    // w_hid as float4: [h][64]
    __shared__ float  s_sn[2][90][10];     // double-buffered sn_in
    __shared__ float  s_wtime[90];
    __shared__ float  s_bias[10];

    const int tid  = threadIdx.x;
    const int warp = tid >> 5;
    const int lane = tid & 31;

    // ---- one-time init: stage weights into smem ----
    const float4* wh4 = reinterpret_cast<const float4*>(w_hid);
    for (int i = tid; i < 640; i += THREADS) s_whid4[i] = wh4[i];
    if (tid < 90) s_wtime[tid] = w_time[tid];
    __syncthreads();
    if (tid < 10) {
        const float* row = reinterpret_cast<const float*>(&s_whid4[tid * 64]);
        float s = 0.f;
        #pragma unroll 8
        for (int d = 0; d < 256; ++d) s += row[d];
        s_bias[tid] = b_hid[tid] + b_ant[0] * s;   // fold conv bias into hidden bias
    }
    const float wa0 = w_ant[0], wa1 = w_ant[1], wa2 = w_ant[2], wa3 = w_ant[3];
    __syncthreads();

    // loop-invariant per-lane reduction metadata
    const int h_mine = (lane & 2) ? (8 + ((lane >> 4) & 1))
                                  : (((lane >> 2) & 1) * 4 + ((lane >> 3) & 1) * 2 + ((lane >> 4) & 1));
    const bool writer = ((lane & 1) == 0) && (((lane & 2) == 0) || ((lane & 12) == 0));
    const float4* wl0 = s_whid4 + lane;   // per-lane weight base (half1 uses +32)

    // produce one timestep t of row base xb into s_sn[buf]
    auto produce_t = [&](const float4* xb, int t, int buf) {
        const float4* xw = xb + t * 256 + lane;
        float acc[10];

        // ---- half 0: all 4 antennas, d-offset 0 ----
        {
            float4 a0 = __ldcs(xw      );
            float4 a1 = __ldcs(xw + 64 );
            float4 a2 = __ldcs(xw + 128);
            float4 a3 = __ldcs(xw + 192);
            float4 f;
            f.x = fmaf(a3.x, wa3, fmaf(a2.x, wa2, fmaf(a1.x, wa1, a0.x * wa0)));
            f.y = fmaf(a3.y, wa3, fmaf(a2.y, wa2, fmaf(a1.y, wa1, a0.y * wa0)));
            f.z = fmaf(a3.z, wa3, fmaf(a2.z, wa2, fmaf(a1.z, wa1, a0.z * wa0)));
            f.w = fmaf(a3.w, wa3, fmaf(a2.w, wa2, fmaf(a1.w, wa1, a0.w * wa0)));
            #pragma unroll
            for (int h = 0; h < 10; ++h) {
                float4 w = wl0[h * 64];
                float r;
                r = f.x * w.x;
                r = fmaf(f.y, w.y, r);
                r = fmaf(f.z, w.z, r);
                r = fmaf(f.w, w.w, r);
                acc[h] = r;
            }
        }

        // ---- half 1: all 4 antennas, d-offset 32 (float4 units) ----
        {
            float4 a0 = __ldcs(xw + 32 );
            float4 a1 = __ldcs(xw + 96 );
            float4 a2 = __ldcs(xw + 160);
            float4 a3 = __ldcs(xw + 224);
            float4 f;
            f.x = fmaf(a3.x, wa3, fmaf(a2.x, wa2, fmaf(a1.x, wa1, a0.x * wa0)));
            f.y = fmaf(a3.y, wa3, fmaf(a2.y, wa2, fmaf(a1.y, wa1, a0.y * wa0)));
            f.z = fmaf(a3.z, wa3, fmaf(a2.z, wa2, fmaf(a1.z, wa1, a0.z * wa0)));
            f.w = fmaf(a3.w, wa3, fmaf(a2.w, wa2, fmaf(a1.w, wa1, a0.w * wa0)));
            #pragma unroll
            for (int h = 0; h < 10; ++h) {
                float4 w = wl0[h * 64 + 32];
                float r = acc[h];
                r = fmaf(f.x, w.x, r);
                r = fmaf(f.y, w.y, r);
                r = fmaf(f.z, w.z, r);
                r = fmaf(f.w, w.w, r);
                acc[h] = r;
            }
        }

        // ---- log-packed warp reduction: 12 SHFL ----
        float v0 = pair_reduce(acc[0], acc[1], 16, lane);
        float v1 = pair_reduce(acc[2], acc[3], 16, lane);
        float v2 = pair_reduce(acc[4], acc[5], 16, lane);
        float v3 = pair_reduce(acc[6], acc[7], 16, lane);
        float v4 = pair_reduce(acc[8], acc[9], 16, lane);
        float u0 = pair_reduce(v0, v1, 8, lane);
        float u1 = pair_reduce(v2, v3, 8, lane);
        v4 += __shfl_xor_sync(0xffffffffu, v4, 8);
        float w0r = pair_reduce(u0, u1, 4, lane);
        v4 += __shfl_xor_sync(0xffffffffu, v4, 4);
        float z = pair_reduce(w0r, v4, 2, lane);
        z += __shfl_xor_sync(0xffffffffu, z, 1);

        if (writer) s_sn[buf][t][h_mine] = z;
    };

    // scan + output for one row (executed by warp 7; lanes < 10 active)
    auto scan_row = [&](int b, int buf) {
        float fused = 0.f;
        if (lane < 10) {
            const int h = lane;
            const float bias = s_bias[h];
            float mem = 0.f, acc = 0.f;
            #pragma unroll 6
            for (int t = 0; t < 90; ++t) {
                float inp = s_sn[buf][t][h] + bias;
                // reset from PREVIOUS mem, reset_mechanism='zero'
                float mem_new = (mem > 1.0f) ? 0.0f : fmaf(0.95f, mem, inp);
                if (mem_new > 1.0f) acc += s_wtime[t];   // spike
                mem = mem_new;
            }
            fused = acc + b_time[0];
        }
        float c0 = (lane < 10) ? fused * __ldg(w_out + lane)      : 0.f;
        float c1 = (lane < 10) ? fused * __ldg(w_out + 10 + lane) : 0.f;
        #pragma unroll
        for (int s = 16; s > 0; s >>= 1) {
            c0 += __shfl_xor_sync(0xffffffffu, c0, s);
            c1 += __shfl_xor_sync(0xffffffffu, c1, s);
        }
        if (lane == 0) {
            float o0 = c0 + b_out[0];
            float o1 = c1 + b_out[1];
            float m  = fmaxf(o0, o1);
            float e0 = __expf(o0 - m);
            float e1 = __expf(o1 - m);
            float inv = 1.0f / (e0 + e1);
            out[2 * b]     = e0 * inv;
            out[2 * b + 1] = e1 * inv;
        }
    };

    // ---- persistent loop over rows ----
    // warps 0-6 each produce 12 timesteps (t = w*12 .. w*12+11);
    // warp 7 scans the previous row, then produces t = 84..89.
    int iter = 0;
    int b;
    for (b = blockIdx.x; b < B; b += gridDim.x, ++iter) {
        const int buf = iter & 1;
        const float4* xb = reinterpret_cast<const float4*>(x) + (size_t)b * 90 * 256;

        if (warp < 7) {
            const int t0 = warp * 12;
            #pragma unroll 2
            for (int t = t0; t < t0 + 12; ++t) produce_t(xb, t, buf);
        } else {
            if (iter > 0) scan_row(b - gridDim.x, buf ^ 1);
            for (int t = 84; t < 90; ++t) produce_t(xb, t, buf);
        }
        __syncthreads();
    }

    // ---- epilogue: scan the final row ----
    if (iter > 0 && warp == 7) {
        scan_row(b - gridDim.x, (iter - 1) & 1);
    }
}

extern "C" void kernel_launch(void* const* d_in, const int* in_sizes, int n_in,
                              void* d_out, int out_size) {
    const float* x      = (const float*)d_in[0];
    const float* w_ant  = (const float*)d_in[1];
    const float* b_ant  = (const float*)d_in[2];
    const float* w_hid  = (const float*)d_in[3];
    const float* b_hid  = (const float*)d_in[4];
    const float* w_time = (const float*)d_in[5];
    const float* b_time = (const float*)d_in[6];
    const float* w_out  = (const float*)d_in[7];
    const float* b_out  = (const float*)d_in[8];
    float* out = (float*)d_out;

    const int B = in_sizes[0] / (90 * 4 * 256);   // 2048
    // occ-5 capacity = 148*5 = 740 slots; 3 rows/CTA -> grid 683, one wave.
    const int rows_per = (B + 739) / 740;                 // 3 for B=2048
    int grid = (B + rows_per - 1) / rows_per;             // 683
    if (grid > B) grid = B;
    snn_fused_kernel<<<grid, THREADS>>>(x, w_ant, b_ant, w_hid, b_hid,
                                        w_time, b_time, w_out, b_out, out, B);
}

// round 16
// speedup vs baseline: 1.2437x; 1.0379x over previous
#include <cuda_runtime.h>
#include <cuda_bf16.h>

#define THREADS 256

// Pair-reduce: lanes with (lane & s)==0 end with full reduction of `a`,
// lanes with (lane & s)!=0 end with full reduction of `b`.
__device__ __forceinline__ float pair_reduce(float a, float b, int s, int lane) {
    bool hi = (lane & s) != 0;
    float send = hi ? a : b;
    float recv = __shfl_xor_sync(0xffffffffu, send, s);
    float keep = hi ? b : a;
    return keep + recv;
}

__device__ __forceinline__ float4 fuse4(float4 a0, float4 a1, float4 a2, float4 a3,
                                        float w0, float w1, float w2, float w3) {
    float4 f;
    f.x = fmaf(a3.x, w3, fmaf(a2.x, w2, fmaf(a1.x, w1, a0.x * w0)));
    f.y = fmaf(a3.y, w3, fmaf(a2.y, w2, fmaf(a1.y, w1, a0.y * w0)));
    f.z = fmaf(a3.z, w3, fmaf(a2.z, w2, fmaf(a1.z, w1, a0.z * w0)));
    f.w = fmaf(a3.w, w3, fmaf(a2.w, w2, fmaf(a1.w, w1, a0.w * w0)));
    return f;
}

__global__ __launch_bounds__(THREADS, 4) void snn_fused_kernel(
    const float* __restrict__ x,       // [B,T,A,D] = [B,90,4,256]
    const float* __restrict__ w_ant,   // [4]
    const float* __restrict__ b_ant,   // scalar
    const float* __restrict__ w_hid,   // [10,256]
    const float* __restrict__ b_hid,   // [10]
    const float* __restrict__ w_time,  // [90]
    const float* __restrict__ b_time,  // scalar
    const float* __restrict__ w_out,   // [2,10]
    const float* __restrict__ b_out,   // [2]
    float* __restrict__ out,           // [B,2]
    int B)
{
    __shared__ float4 s_whid4[10 * 64];    // w_hid as float4: [h][64]
    __shared__ float  s_sn[2][90][10];     // double-buffered sn_in
    __shared__ float  s_wtime[90];
    __shared__ float  s_bias[10];

    const int tid  = threadIdx.x;
    const int warp = tid >> 5;
    const int lane = tid & 31;

    // ---- one-time init: stage weights into smem ----
    const float4* wh4 = reinterpret_cast<const float4*>(w_hid);
    for (int i = tid; i < 640; i += THREADS) s_whid4[i] = wh4[i];
    if (tid < 90) s_wtime[tid] = w_time[tid];
    __syncthreads();
    if (tid < 10) {
        const float* row = reinterpret_cast<const float*>(&s_whid4[tid * 64]);
        float s = 0.f;
        #pragma unroll 8
        for (int d = 0; d < 256; ++d) s += row[d];
        s_bias[tid] = b_hid[tid] + b_ant[0] * s;   // fold conv bias into hidden bias
    }
    const float wa0 = w_ant[0], wa1 = w_ant[1], wa2 = w_ant[2], wa3 = w_ant[3];
    __syncthreads();

    // loop-invariant per-lane reduction metadata
    const int h_mine = (lane & 2) ? (8 + ((lane >> 4) & 1))
                                  : (((lane >> 2) & 1) * 4 + ((lane >> 3) & 1) * 2 + ((lane >> 4) & 1));
    const bool writer = ((lane & 1) == 0) && (((lane & 2) == 0) || ((lane & 12) == 0));
    const float4* wl0 = s_whid4 + lane;   // per-lane weight base (half1 uses +32)

    // warp-reduce 10 partials to packed form; returns z, writer lane stores
    auto reduce_store = [&](float acc[10], int t, int buf) {
        float v0 = pair_reduce(acc[0], acc[1], 16, lane);
        float v1 = pair_reduce(acc[2], acc[3], 16, lane);
        float v2 = pair_reduce(acc[4], acc[5], 16, lane);
        float v3 = pair_reduce(acc[6], acc[7], 16, lane);
        float v4 = pair_reduce(acc[8], acc[9], 16, lane);
        float u0 = pair_reduce(v0, v1, 8, lane);
        float u1 = pair_reduce(v2, v3, 8, lane);
        v4 += __shfl_xor_sync(0xffffffffu, v4, 8);
        float w0r = pair_reduce(u0, u1, 4, lane);
        v4 += __shfl_xor_sync(0xffffffffu, v4, 4);
        float z = pair_reduce(w0r, v4, 2, lane);
        z += __shfl_xor_sync(0xffffffffu, z, 1);
        if (writer) s_sn[buf][t][h_mine] = z;
    };

    // scan + output for one row (warp 7; lanes < 10 active in the recurrence)
    auto scan_row = [&](int b, int buf) {
        float fused = 0.f;
        if (lane < 10) {
            const int h = lane;
            const float bias = s_bias[h];
            float mem = 0.f, acc = 0.f;
            #pragma unroll 6
            for (int t = 0; t < 90; ++t) {
                float inp = s_sn[buf][t][h] + bias;
                // reset from PREVIOUS mem, reset_mechanism='zero'
                float mem_new = (mem > 1.0f) ? 0.0f : fmaf(0.95f, mem, inp);
                if (mem_new > 1.0f) acc += s_wtime[t];   // spike
                mem = mem_new;
            }
            fused = acc + b_time[0];
        }
        float c0 = (lane < 10) ? fused * __ldg(w_out + lane)      : 0.f;
        float c1 = (lane < 10) ? fused * __ldg(w_out + 10 + lane) : 0.f;
        #pragma unroll
        for (int s = 16; s > 0; s >>= 1) {
            c0 += __shfl_xor_sync(0xffffffffu, c0, s);
            c1 += __shfl_xor_sync(0xffffffffu, c1, s);
        }
        if (lane == 0) {
            float o0 = c0 + b_out[0];
            float o1 = c1 + b_out[1];
            float m  = fmaxf(o0, o1);
            float e0 = __expf(o0 - m);
            float e1 = __expf(o1 - m);
            float inv = 1.0f / (e0 + e1);
            out[2 * b]     = e0 * inv;
            out[2 * b + 1] = e1 * inv;
        }
    };

    // ---- persistent loop: warps 0-6 produce timestep PAIRS, warp 7 scans ----
    int iter = 0;
    int b;
    for (b = blockIdx.x; b < B; b += gridDim.x, ++iter) {
        const int buf = iter & 1;

        if (warp < 7) {
            const float4* xb = reinterpret_cast<const float4*>(x) + (size_t)b * 90 * 256;
            // 45 pairs over 7 warps
            for (int p = warp; p < 45; p += 7) {
                const int t0 = 2 * p;
                const float4* xw0 = xb + t0 * 256 + lane;   // timestep t0
                const float4* xw1 = xw0 + 256;              // timestep t0+1
                float acc0[10], acc1[10];

                // ---- half 0 of BOTH timesteps: 8 LDG.128 in flight ----
                {
                    float4 a0 = __ldcs(xw0      );
                    float4 a1 = __ldcs(xw0 + 64 );
                    float4 a2 = __ldcs(xw0 + 128);
                    float4 a3 = __ldcs(xw0 + 192);
                    float4 c0 = __ldcs(xw1      );
                    float4 c1 = __ldcs(xw1 + 64 );
                    float4 c2 = __ldcs(xw1 + 128);
                    float4 c3 = __ldcs(xw1 + 192);
                    float4 f = fuse4(a0, a1, a2, a3, wa0, wa1, wa2, wa3);
                    float4 g = fuse4(c0, c1, c2, c3, wa0, wa1, wa2, wa3);
                    #pragma unroll
                    for (int h = 0; h < 10; ++h) {
                        float4 w = wl0[h * 64];            // shared by both t's
                        float r0, r1;
                        r0 = f.x * w.x;
                        r1 = g.x * w.x;
                        r0 = fmaf(f.y, w.y, r0);
                        r1 = fmaf(g.y, w.y, r1);
                        r0 = fmaf(f.z, w.z, r0);
                        r1 = fmaf(g.z, w.z, r1);
                        r0 = fmaf(f.w, w.w, r0);
                        r1 = fmaf(g.w, w.w, r1);
                        acc0[h] = r0;
                        acc1[h] = r1;
                    }
                }

                // ---- half 1 of BOTH timesteps ----
                {
                    float4 a0 = __ldcs(xw0 + 32 );
                    float4 a1 = __ldcs(xw0 + 96 );
                    float4 a2 = __ldcs(xw0 + 160);
                    float4 a3 = __ldcs(xw0 + 224);
                    float4 c0 = __ldcs(xw1 + 32 );
                    float4 c1 = __ldcs(xw1 + 96 );
                    float4 c2 = __ldcs(xw1 + 160);
                    float4 c3 = __ldcs(xw1 + 224);
                    float4 f = fuse4(a0, a1, a2, a3, wa0, wa1, wa2, wa3);
                    float4 g = fuse4(c0, c1, c2, c3, wa0, wa1, wa2, wa3);
                    #pragma unroll
                    for (int h = 0; h < 10; ++h) {
                        float4 w = wl0[h * 64 + 32];       // shared by both t's
                        float r0 = acc0[h], r1 = acc1[h];
                        r0 = fmaf(f.x, w.x, r0);
                        r1 = fmaf(g.x, w.x, r1);
                        r0 = fmaf(f.y, w.y, r0);
                        r1 = fmaf(g.y, w.y, r1);
                        r0 = fmaf(f.z, w.z, r0);
                        r1 = fmaf(g.z, w.z, r1);
                        r0 = fmaf(f.w, w.w, r0);
                        r1 = fmaf(g.w, w.w, r1);
                        acc0[h] = r0;
                        acc1[h] = r1;
                    }
                }

                reduce_store(acc0, t0,     buf);
                reduce_store(acc1, t0 + 1, buf);
            }
        } else {
            // warp 7: scan the previous row (produced last iteration)
            if (iter > 0) scan_row(b - gridDim.x, buf ^ 1);
        }
        __syncthreads();
    }

    // ---- epilogue: scan the final row ----
    if (iter > 0 && warp == 7) {
        scan_row(b - gridDim.x, (iter - 1) & 1);
    }
}

extern "C" void kernel_launch(void* const* d_in, const int* in_sizes, int n_in,
                              void* d_out, int out_size) {
    const float* x      = (const float*)d_in[0];
    const float* w_ant  = (const float*)d_in[1];
    const float* b_ant  = (const float*)d_in[2];
    const float* w_hid  = (const float*)d_in[3];
    const float* b_hid  = (const float*)d_in[4];
    const float* w_time = (const float*)d_in[5];
    const float* b_time = (const float*)d_in[6];
    const float* w_out  = (const float*)d_in[7];
    const float* b_out  = (const float*)d_in[8];
    float* out = (float*)d_out;

    const int B = in_sizes[0] / (90 * 4 * 256);   // 2048
    // occ-4: 148*4 = 592 CTAs, exactly 4 resident per SM, one wave.
    // Grid-stride rows: blocks 0-271 take 4 rows, 272-591 take 3 ->
    // per-SM 13-14 rows under modular placement (ideal 13.8).
    int grid = 592;
    if (grid > B) grid = B;
    snn_fused_kernel<<<grid, THREADS>>>(x, w_ant, b_ant, w_hid, b_hid,
                                        w_time, b_time, w_out, b_out, out, B);
}